// round 5
// baseline (speedup 1.0000x reference)
#include <cuda_runtime.h>
#include <cmath>
#include <stdint.h>

#define AMAX 1024
#define WORDS 32
#define BMAX 2
#define CMAX 80
#define NK 8           // compact neighbor-list capacity (per box)

// Scratch (static device arrays; no dynamic allocation allowed)
__device__ unsigned g_adjT[BMAX * WORDS * AMAX];          // 256 KB (fallback, degree>NK)
__device__ unsigned short g_nbr[BMAX * AMAX * NK];        // 32 KB compact neighbor lists
__device__ int g_ncnt[BMAX * AMAX];                       // 8 KB degrees
__device__ int g_done;                                    // producer completion counter
__device__ int g_ack;                                     // consumer ack (for replay-safe reset)

__device__ __forceinline__ float4 regress_box(const float* __restrict__ reg,
                                              const float* __restrict__ anchors,
                                              int b, int t, int A, float Wf, float Hf) {
    float ax1 = anchors[4 * t + 0], ay1 = anchors[4 * t + 1];
    float ax2 = anchors[4 * t + 2], ay2 = anchors[4 * t + 3];
    float w = ax2 - ax1, h = ay2 - ay1;
    float cx = ax1 + 0.5f * w, cy = ay1 + 0.5f * h;
    const float* rb = reg + (size_t)b * 4 * A;
    float dx = rb[0 * A + t] * 0.1f;
    float dy = rb[1 * A + t] * 0.1f;
    float dw = rb[2 * A + t] * 0.2f;
    float dh = rb[3 * A + t] * 0.2f;
    float pcx = cx + dx * w, pcy = cy + dy * h;
    float pw = expf(dw) * w, ph = expf(dh) * h;
    float4 r;
    r.x = fmaxf(pcx - 0.5f * pw, 0.0f);
    r.y = fmaxf(pcy - 0.5f * ph, 0.0f);
    r.z = fminf(pcx + 0.5f * pw, Wf);
    r.w = fminf(pcy + 0.5f * ph, Hf);
    return r;
}

// Single fused kernel. Grid = B*C blocks of 1024 threads, one (b,c) each.
// Blocks [0, B*32) FIRST produce the per-batch IoU adjacency (warp-per-row,
// 32 rows per block) into g_adjT/g_nbr/g_ncnt, then join everyone in the NMS
// phase. All blocks co-resident (2/SM) -> spin handoff cannot deadlock.
__global__ void __launch_bounds__(1024, 2) fused_kernel(
    const float* __restrict__ cls, const float* __restrict__ reg,
    const float* __restrict__ anchors, float* __restrict__ out,
    int A, int C, int nProd, int nBlocks, float Wf, float Hf) {
    __shared__ float4 sbox[AMAX];                 // 16 KB (reused: adj boxes -> nms boxes)
    __shared__ float ssc[AMAX];                   // 4 KB
    __shared__ volatile unsigned char skept[AMAX];
    __shared__ volatile unsigned char sdec[AMAX];
    int bid = blockIdx.x;
    int i = threadIdx.x;
    int lane = i & 31, wid = i >> 5;
    int b = bid / C;

    // ---------------- Phase 1: adjacency producers ----------------
    if (bid < nProd) {
        int ab = bid >> 5;            // adjacency batch
        int chunk = bid & 31;         // 32 rows per block
        sbox[i] = regress_box(reg, anchors, ab, i, A, Wf, Hf);
        __syncthreads();

        int row = chunk * 32 + wid;
        float4 bi = sbox[row];
        float ai = (bi.z - bi.x) * (bi.w - bi.y);
        unsigned mybits = 0;
        #pragma unroll
        for (int w = 0; w < WORDS; ++w) {
            float4 bj = sbox[w * 32 + lane];
            float ix1 = fmaxf(bi.x, bj.x), iy1 = fmaxf(bi.y, bj.y);
            float ix2 = fminf(bi.z, bj.z), iy2 = fminf(bi.w, bj.w);
            float inter = fmaxf(ix2 - ix1, 0.0f) * fmaxf(iy2 - iy1, 0.0f);
            float aj = (bj.z - bj.x) * (bj.w - bj.y);
            float den = fmaxf((ai + aj) - inter, 1e-9f);
            bool adj = __fdiv_rn(inter, den) > 0.5f;  // IEEE div: match XLA at 0.5
            unsigned bal = __ballot_sync(0xffffffffu, adj);
            if (lane == w) mybits = bal;
        }
        unsigned m = mybits;
        if (lane == (row >> 5)) m &= ~(1u << (row & 31));     // drop self bit
        g_adjT[((size_t)ab * WORDS + lane) * AMAX + row] = m; // transposed, self-free

        // Compact neighbor list via shuffle prefix-sum of per-lane popcounts.
        int cnt = __popc(m);
        int scan = cnt;
        #pragma unroll
        for (int d = 1; d < 32; d <<= 1) {
            int t = __shfl_up_sync(0xffffffffu, scan, d);
            if (lane >= d) scan += t;
        }
        int excl = scan - cnt;
        int tot = __shfl_sync(0xffffffffu, scan, 31);
        unsigned short* np = g_nbr + ((size_t)ab * AMAX + row) * NK;
        unsigned mm = m;
        int pos = excl;
        while (mm && pos < NK) {
            int t2 = __ffs(mm) - 1; mm &= mm - 1;
            np[pos++] = (unsigned short)(lane * 32 + t2);
        }
        if (lane == 0) g_ncnt[ab * AMAX + row] = tot;

        __syncthreads();              // everyone done reading sbox before reuse
        __threadfence();              // publish adjacency before signaling
        if (i == 0) atomicAdd(&g_done, 1);
    }

    // ---------------- Phase 2: NMS (all blocks) ----------------
    // Stage inputs; box regression overlaps the producer wait.
    float s = cls[(size_t)bid * AMAX + i];
    float4 mybox = regress_box(reg, anchors, b, i, A, Wf, Hf);
    ssc[i] = s;
    sbox[i] = mybox;
    sdec[i] = 0;
    skept[i] = 0;

    if (i == 0) {
        while (atomicAdd(&g_done, 0) < nProd) { }
        __threadfence();
        int a = atomicAdd(&g_ack, 1);
        if (a == nBlocks - 1) {       // last block past the wait: safe to reset
            atomicExch(&g_done, 0);
            atomicExch(&g_ack, 0);
        }
    }
    __syncthreads();                  // adjacency visible; smem state initialized

    int total = g_ncnt[b * AMAX + i];
    uint4 nv = *(const uint4*)&g_nbr[((size_t)b * AMAX + i) * NK];
    bool ovf = total > NK;            // rare high-degree fallback
    int cnt = ovf ? 0 : total;

    // Higher-ranked neighbors (score desc, index asc) into registers.
    unsigned short js[NK];
    int nh = 0;
    {
        unsigned words[4] = {nv.x, nv.y, nv.z, nv.w};
        #pragma unroll
        for (int k = 0; k < NK; ++k) {
            if (k < cnt) {
                int j = (words[k >> 1] >> ((k & 1) * 16)) & 0xFFFF;
                float sj = ssc[j];
                if (sj > s || (sj == s && j < i)) js[nh++] = (unsigned short)j;
            }
        }
    }

    bool valid = s > 0.05f;
    if (!valid) {
        sdec[i] = 1;                                   // never kept, never suppresses
    } else if (!ovf && nh == 0) {
        skept[i] = 1; __threadfence_block(); sdec[i] = 1;
    } else {
        // Async monotone dataflow: spin until all higher neighbors decided or
        // one kept. Min-rank undecided always progresses -> no deadlock.
        const unsigned* adjT = g_adjT + (size_t)b * WORDS * AMAX;
        for (;;) {
            bool sup = false, alld = true;
            if (!ovf) {
                unsigned dmask = 0;
                for (int k = 0; k < nh; ++k)
                    if (sdec[js[k]]) dmask |= 1u << k; else alld = false;
                __threadfence_block();                 // acquire: dec before kept
                while (dmask) {
                    int k = __ffs(dmask) - 1; dmask &= dmask - 1;
                    if (skept[js[k]]) { sup = true; break; }
                }
            } else {
                #pragma unroll
                for (int w = 0; w < WORDS; ++w) {
                    unsigned mm = adjT[w * AMAX + i];
                    while (mm) {
                        int bit = __ffs(mm) - 1; mm &= mm - 1;
                        int j = w * 32 + bit;
                        float sj = ssc[j];
                        if (sj > s || (sj == s && j < i)) {
                            if (sdec[j]) {
                                __threadfence_block();
                                if (skept[j]) sup = true;
                            } else alld = false;
                        }
                    }
                }
            }
            if (sup)  { sdec[i] = 1; break; }
            if (alld) { skept[i] = 1; __threadfence_block(); sdec[i] = 1; break; }
        }
    }
    __syncthreads();  // all decided; skept[] stable for the output pass

    // Fused output as float4 stores: 5120 floats/block = 1280 float4.
    const float* sboxf = (const float*)sbox;
    float4* obase4 = (float4*)(out + (size_t)bid * AMAX * 5);
    #pragma unroll
    for (int r = 0; r < 2; ++r) {
        int t = r * 1024 + i;
        if (t < (AMAX * 5) / 4) {
            float4 v;
            float* vf = (float*)&v;
            #pragma unroll
            for (int k = 0; k < 4; ++k) {
                int idx = t * 4 + k;
                int a = idx / 5;
                int f = idx - a * 5;
                float x = 0.0f;
                if (skept[a]) x = (f == 0) ? ssc[a] : sboxf[a * 4 + (f - 1)];
                vf[k] = x;
            }
            obase4[t] = v;
        }
    }
}

extern "C" void kernel_launch(void* const* d_in, const int* in_sizes, int n_in,
                              void* d_out, int out_size) {
    // metadata order: image, cls_pred, reg_pred, anchors
    const float* cls = (const float*)d_in[1];
    const float* reg = (const float*)d_in[2];
    const float* anchors = (const float*)d_in[3];

    int A = in_sizes[3] / 4;                 // 1024
    int B = in_sizes[2] / (4 * A);           // 2
    int C = in_sizes[1] / (B * A);           // 80
    long long hw = (long long)in_sizes[0] / (3LL * B);
    int H = (int)(sqrt((double)hw) + 0.5);   // 2048 (image used for shape only)
    float Hf = (float)H, Wf = (float)H;

    int nProd = B * 32;                      // 64 adjacency producer blocks
    int nBlocks = B * C;                     // 160 total blocks (>= nProd)
    fused_kernel<<<nBlocks, 1024>>>(cls, reg, anchors, (float*)d_out,
                                    A, C, nProd, nBlocks, Wf, Hf);
}

// round 6
// speedup vs baseline: 1.0960x; 1.0960x over previous
#include <cuda_runtime.h>
#include <cmath>
#include <stdint.h>

#define AMAX 1024
#define WORDS 32
#define BMAX 2
#define CMAX 80
#define NK 8           // compact neighbor-list capacity (per box)

// Scratch (static device arrays; no dynamic allocation allowed)
__device__ unsigned g_adjT[BMAX * WORDS * AMAX];          // 256 KB (fallback, degree>NK)
__device__ unsigned short g_nbr[BMAX * AMAX * NK];        // 32 KB compact neighbor lists
__device__ int g_ncnt[BMAX * AMAX];                       // 8 KB degrees
__device__ int g_done[BMAX];                              // per-batch producer counters
__device__ int g_ack;                                     // replay-safe reset counter

__device__ __forceinline__ float4 regress_box(const float* __restrict__ reg,
                                              const float* __restrict__ anchors,
                                              int b, int t, int A, float Wf, float Hf) {
    float ax1 = anchors[4 * t + 0], ay1 = anchors[4 * t + 1];
    float ax2 = anchors[4 * t + 2], ay2 = anchors[4 * t + 3];
    float w = ax2 - ax1, h = ay2 - ay1;
    float cx = ax1 + 0.5f * w, cy = ay1 + 0.5f * h;
    const float* rb = reg + (size_t)b * 4 * A;
    float dx = rb[0 * A + t] * 0.1f;
    float dy = rb[1 * A + t] * 0.1f;
    float dw = rb[2 * A + t] * 0.2f;
    float dh = rb[3 * A + t] * 0.2f;
    float pcx = cx + dx * w, pcy = cy + dy * h;
    float pw = expf(dw) * w, ph = expf(dh) * h;
    float4 r;
    r.x = fmaxf(pcx - 0.5f * pw, 0.0f);
    r.y = fmaxf(pcy - 0.5f * ph, 0.0f);
    r.z = fminf(pcx + 0.5f * pw, Wf);
    r.w = fminf(pcy + 0.5f * ph, Hf);
    return r;
}

// One fused kernel. Grid = B*C blocks x 1024 threads, one (b,c) each.
// Every block: regress own batch's boxes (reused for NMS + output), produce
// its ~13 assigned adjacency rows, signal per-batch counter, wait (volatile
// poll + nanosleep) for its batch's C producers, run async-dataflow NMS,
// write coalesced float4 output.
__global__ void __launch_bounds__(1024, 2) fused_kernel(
    const float* __restrict__ cls, const float* __restrict__ reg,
    const float* __restrict__ anchors, float* __restrict__ out,
    int A, int C, int nBlocks, float Wf, float Hf) {
    __shared__ float4 sbox[AMAX];                   // 16 KB
    __shared__ float ssc[AMAX];                     // 4 KB
    __shared__ volatile unsigned char sstate[AMAX]; // 0=undec, 1=dropped, 2=kept
    int bid = blockIdx.x;
    int i = threadIdx.x;
    int lane = i & 31, wid = i >> 5;
    int b = bid / C;
    int c = bid - b * C;
    int RPB = (A + C - 1) / C;        // adjacency rows per block (13)

    // Stage: regress own batch boxes (used by phase 1 AND phase 2) + scores.
    float s = cls[(size_t)bid * AMAX + i];
    sbox[i] = regress_box(reg, anchors, b, i, A, Wf, Hf);
    ssc[i] = s;
    sstate[i] = 0;
    __syncthreads();

    // ---------------- Phase 1: produce assigned adjacency rows ----------------
    int row = c * RPB + wid;          // warp wid -> row (wid >= RPB idle)
    if (wid < RPB && row < AMAX) {
        float4 bi = sbox[row];
        float ai = (bi.z - bi.x) * (bi.w - bi.y);
        unsigned mybits = 0;
        #pragma unroll
        for (int w = 0; w < WORDS; ++w) {
            float4 bj = sbox[w * 32 + lane];
            float ix1 = fmaxf(bi.x, bj.x), iy1 = fmaxf(bi.y, bj.y);
            float ix2 = fminf(bi.z, bj.z), iy2 = fminf(bi.w, bj.w);
            float inter = fmaxf(ix2 - ix1, 0.0f) * fmaxf(iy2 - iy1, 0.0f);
            float aj = (bj.z - bj.x) * (bj.w - bj.y);
            float den = fmaxf((ai + aj) - inter, 1e-9f);
            bool adj = __fdiv_rn(inter, den) > 0.5f;  // IEEE div: match XLA at 0.5
            unsigned bal = __ballot_sync(0xffffffffu, adj);
            if (lane == w) mybits = bal;
        }
        unsigned m = mybits;
        if (lane == (row >> 5)) m &= ~(1u << (row & 31));    // drop self bit
        g_adjT[((size_t)b * WORDS + lane) * AMAX + row] = m; // transposed, self-free

        // Compact neighbor list via shuffle prefix-sum of per-lane popcounts.
        int cnt = __popc(m);
        int scan = cnt;
        #pragma unroll
        for (int d = 1; d < 32; d <<= 1) {
            int t = __shfl_up_sync(0xffffffffu, scan, d);
            if (lane >= d) scan += t;
        }
        int excl = scan - cnt;
        int tot = __shfl_sync(0xffffffffu, scan, 31);
        unsigned short* np = g_nbr + ((size_t)b * AMAX + row) * NK;
        unsigned mm = m;
        int pos = excl;
        while (mm && pos < NK) {
            int t2 = __ffs(mm) - 1; mm &= mm - 1;
            np[pos++] = (unsigned short)(lane * 32 + t2);
        }
        if (lane == 0) g_ncnt[b * AMAX + row] = tot;
    }
    __syncthreads();                  // all rows of this block written
    __threadfence();                  // publish before signaling
    if (i == 0) atomicAdd(&g_done[b], 1);

    // ---------------- Handoff: wait for this batch's C producers ----------------
    if (i == 0) {
        volatile int* dp = &g_done[b];
        while (*dp < C) __nanosleep(128);   // read-only poll, no LTS RMW contention
        __threadfence();
        int a = atomicAdd(&g_ack, 1);
        if (a == nBlocks - 1) {             // last block past its wait: safe reset
            g_done[0] = 0; g_done[1] = 0;
            __threadfence();
            atomicExch(&g_ack, 0);
        }
    }
    __syncthreads();                  // adjacency for batch b now visible

    // ---------------- Phase 2: async monotone-dataflow NMS ----------------
    int total = g_ncnt[b * AMAX + i];
    uint4 nv = *(const uint4*)&g_nbr[((size_t)b * AMAX + i) * NK];
    bool ovf = total > NK;            // rare high-degree fallback
    int cnt = ovf ? 0 : total;

    // Higher-ranked neighbors (score desc, index asc) into registers.
    unsigned short js[NK];
    int nh = 0;
    {
        unsigned words[4] = {nv.x, nv.y, nv.z, nv.w};
        #pragma unroll
        for (int k = 0; k < NK; ++k) {
            if (k < cnt) {
                int j = (words[k >> 1] >> ((k & 1) * 16)) & 0xFFFF;
                float sj = ssc[j];
                if (sj > s || (sj == s && j < i)) js[nh++] = (unsigned short)j;
            }
        }
    }

    bool valid = s > 0.05f;
    if (!valid) {
        sstate[i] = 1;                // never kept, never suppresses
    } else if (!ovf && nh == 0) {
        sstate[i] = 2;                // top of its chain: kept
    } else {
        // Spin until all higher neighbors decided or one of them kept.
        // Single monotone byte per box (0 -> 1|2): one LDS per hop, no fences.
        // Min-rank undecided box always has all higher nbrs decided -> progress.
        const unsigned* adjT = g_adjT + (size_t)b * WORDS * AMAX;
        for (;;) {
            bool sup = false, alld = true;
            if (!ovf) {
                for (int k = 0; k < nh; ++k) {
                    unsigned char v = sstate[js[k]];
                    if (v == 2) { sup = true; break; }
                    if (v == 0) alld = false;
                }
            } else {
                #pragma unroll
                for (int w = 0; w < WORDS; ++w) {
                    unsigned mm = adjT[w * AMAX + i];
                    while (mm) {
                        int bit = __ffs(mm) - 1; mm &= mm - 1;
                        int j = w * 32 + bit;
                        float sj = ssc[j];
                        if (sj > s || (sj == s && j < i)) {
                            unsigned char v = sstate[j];
                            if (v == 2) { sup = true; }
                            else if (v == 0) alld = false;
                        }
                    }
                    if (sup) break;
                }
            }
            if (sup)  { sstate[i] = 1; break; }
            if (alld) { sstate[i] = 2; break; }
        }
    }
    __syncthreads();                  // all decided; sstate stable

    // Coalesced float4 output: 5120 floats/block = 1280 float4.
    const float* sboxf = (const float*)sbox;
    float4* obase4 = (float4*)(out + (size_t)bid * AMAX * 5);
    #pragma unroll
    for (int r = 0; r < 2; ++r) {
        int t = r * 1024 + i;
        if (t < (AMAX * 5) / 4) {
            float4 v;
            float* vf = (float*)&v;
            #pragma unroll
            for (int k = 0; k < 4; ++k) {
                int idx = t * 4 + k;
                int a = idx / 5;
                int f = idx - a * 5;
                float x = 0.0f;
                if (sstate[a] == 2) x = (f == 0) ? ssc[a] : sboxf[a * 4 + (f - 1)];
                vf[k] = x;
            }
            obase4[t] = v;
        }
    }
}

extern "C" void kernel_launch(void* const* d_in, const int* in_sizes, int n_in,
                              void* d_out, int out_size) {
    // metadata order: image, cls_pred, reg_pred, anchors
    const float* cls = (const float*)d_in[1];
    const float* reg = (const float*)d_in[2];
    const float* anchors = (const float*)d_in[3];

    int A = in_sizes[3] / 4;                 // 1024
    int B = in_sizes[2] / (4 * A);           // 2
    int C = in_sizes[1] / (B * A);           // 80
    long long hw = (long long)in_sizes[0] / (3LL * B);
    int H = (int)(sqrt((double)hw) + 0.5);   // 2048 (image used for shape only)
    float Hf = (float)H, Wf = (float)H;

    int nBlocks = B * C;                     // 160 blocks, all co-resident (2/SM)
    fused_kernel<<<nBlocks, 1024>>>(cls, reg, anchors, (float*)d_out,
                                    A, C, nBlocks, Wf, Hf);
}

// round 7
// speedup vs baseline: 1.3643x; 1.2448x over previous
#include <cuda_runtime.h>
#include <cmath>
#include <stdint.h>

#define AMAX 1024
#define WORDS 32
#define BMAX 2
#define CMAX 80
#define NK 8           // compact neighbor-list capacity (per box)

// Scratch (static device arrays; no dynamic allocation allowed)
__device__ unsigned g_adjT[BMAX * WORDS * AMAX];          // 256 KB (fallback, degree>NK)
__device__ unsigned short g_nbr[BMAX * AMAX * NK];        // 32 KB compact neighbor lists
__device__ int g_ncnt[BMAX * AMAX];                       // 8 KB degrees
__device__ int g_done[BMAX];                              // per-batch producer counters
__device__ int g_ack;                                     // replay-safe reset counter

__device__ __forceinline__ float4 regress_box(const float* __restrict__ reg,
                                              const float* __restrict__ anchors,
                                              int b, int t, int A, float Wf, float Hf) {
    float ax1 = anchors[4 * t + 0], ay1 = anchors[4 * t + 1];
    float ax2 = anchors[4 * t + 2], ay2 = anchors[4 * t + 3];
    float w = ax2 - ax1, h = ay2 - ay1;
    float cx = ax1 + 0.5f * w, cy = ay1 + 0.5f * h;
    const float* rb = reg + (size_t)b * 4 * A;
    float dx = rb[0 * A + t] * 0.1f;
    float dy = rb[1 * A + t] * 0.1f;
    float dw = rb[2 * A + t] * 0.2f;
    float dh = rb[3 * A + t] * 0.2f;
    float pcx = cx + dx * w, pcy = cy + dy * h;
    float pw = expf(dw) * w, ph = expf(dh) * h;
    float4 r;
    r.x = fmaxf(pcx - 0.5f * pw, 0.0f);
    r.y = fmaxf(pcy - 0.5f * ph, 0.0f);
    r.z = fminf(pcx + 0.5f * pw, Wf);
    r.w = fminf(pcy + 0.5f * ph, Hf);
    return r;
}

// One fused kernel. Grid = B*C blocks x 1024 threads, one (b,c) each.
// Every block: regress own batch's boxes, produce its 13 adjacency rows
// (2 rows/warp, candidate-filtered exact IoU), signal per-batch counter,
// wait, run async-dataflow NMS, write coalesced float4 output.
__global__ void __launch_bounds__(1024, 2) fused_kernel(
    const float* __restrict__ cls, const float* __restrict__ reg,
    const float* __restrict__ anchors, float* __restrict__ out,
    int A, int C, int nBlocks, float Wf, float Hf) {
    __shared__ float4 sbox[AMAX];                   // 16 KB
    __shared__ float ssc[AMAX];                     // 4 KB
    __shared__ volatile unsigned char sstate[AMAX]; // 0=undec, 1=dropped, 2=kept
    int bid = blockIdx.x;
    int i = threadIdx.x;
    int lane = i & 31, wid = i >> 5;
    int b = bid / C;
    int c = bid - b * C;
    const int RPB = 13;               // ceil(1024/80) adjacency rows per block

    // Stage: regress own batch boxes (used by phase 1 AND phase 2) + scores.
    float s = cls[(size_t)bid * AMAX + i];
    sbox[i] = regress_box(reg, anchors, b, i, A, Wf, Hf);
    ssc[i] = s;
    sstate[i] = 0;
    __syncthreads();

    // -------- Phase 1: produce assigned adjacency rows (2 rows per warp) --------
    int r0 = c * RPB + 2 * wid;
    if (2 * wid < RPB && r0 < AMAX) {
        bool has1 = (2 * wid + 1 < RPB) && (r0 + 1 < AMAX);
        float4 b0 = sbox[r0];
        float4 b1 = has1 ? sbox[r0 + 1] : b0;
        float a0 = (b0.z - b0.x) * (b0.w - b0.y);
        float a1 = (b1.z - b1.x) * (b1.w - b1.y);
        unsigned bits0 = 0, bits1 = 0;
        #pragma unroll 4
        for (int w = 0; w < WORDS; ++w) {
            float4 bj = sbox[w * 32 + lane];
            float ajj = (bj.z - bj.x) * (bj.w - bj.y);
            float i0 = fmaxf(fminf(b0.z, bj.z) - fmaxf(b0.x, bj.x), 0.0f) *
                       fmaxf(fminf(b0.w, bj.w) - fmaxf(b0.y, bj.y), 0.0f);
            float i1 = fmaxf(fminf(b1.z, bj.z) - fmaxf(b1.x, bj.x), 0.0f) *
                       fmaxf(fminf(b1.w, bj.w) - fmaxf(b1.y, bj.y), 0.0f);
            // Conservative candidate filter: IoU>0.5 => 3*inter > a+aj (real
            // arithmetic); 0.999 margin absorbs fp rounding. Exact decision
            // still made by the IEEE division below -> bit-identical results.
            bool c0 = 3.0f * i0 >= 0.999f * (a0 + ajj);
            bool c1 = 3.0f * i1 >= 0.999f * (a1 + ajj);
            bool adj0 = false, adj1 = false;
            if (__any_sync(0xffffffffu, c0 || c1)) {   // rare path (~13% of iters)
                if (c0) adj0 = __fdiv_rn(i0, fmaxf((a0 + ajj) - i0, 1e-9f)) > 0.5f;
                if (c1) adj1 = __fdiv_rn(i1, fmaxf((a1 + ajj) - i1, 1e-9f)) > 0.5f;
            }
            unsigned bal0 = __ballot_sync(0xffffffffu, adj0);
            unsigned bal1 = __ballot_sync(0xffffffffu, adj1);
            if (lane == w) { bits0 = bal0; bits1 = bal1; }
        }
        // Emit both rows: transposed bit-matrix + compact neighbor list.
        #pragma unroll
        for (int rr = 0; rr < 2; ++rr) {
            int row = r0 + rr;
            if (rr == 1 && !has1) break;
            unsigned m = rr ? bits1 : bits0;
            if (lane == (row >> 5)) m &= ~(1u << (row & 31));    // drop self bit
            g_adjT[((size_t)b * WORDS + lane) * AMAX + row] = m;

            int cnt = __popc(m);
            int scan = cnt;
            #pragma unroll
            for (int d = 1; d < 32; d <<= 1) {
                int t = __shfl_up_sync(0xffffffffu, scan, d);
                if (lane >= d) scan += t;
            }
            int excl = scan - cnt;
            int tot = __shfl_sync(0xffffffffu, scan, 31);
            unsigned short* np = g_nbr + ((size_t)b * AMAX + row) * NK;
            unsigned mm = m;
            int pos = excl;
            while (mm && pos < NK) {
                int t2 = __ffs(mm) - 1; mm &= mm - 1;
                np[pos++] = (unsigned short)(lane * 32 + t2);
            }
            if (lane == 0) g_ncnt[b * AMAX + row] = tot;
        }
    }
    __syncthreads();                  // all this block's rows written (intra-CTA HB)
    if (i == 0) {
        __threadfence();              // release (thread 0 only; bar gives CTA HB)
        atomicAdd(&g_done[b], 1);
        volatile int* dp = &g_done[b];
        while (*dp < C) __nanosleep(64);   // read-only poll
        __threadfence();              // acquire
        int a = atomicAdd(&g_ack, 1);
        if (a == nBlocks - 1) {       // last block past its wait: safe reset
            g_done[0] = 0; g_done[1] = 0;
            __threadfence();
            atomicExch(&g_ack, 0);
        }
    }
    __syncthreads();                  // adjacency for batch b now visible to block

    // ---------------- Phase 2: async monotone-dataflow NMS ----------------
    int total = g_ncnt[b * AMAX + i];
    uint4 nv = *(const uint4*)&g_nbr[((size_t)b * AMAX + i) * NK];
    bool ovf = total > NK;            // rare high-degree fallback
    int cnt = ovf ? 0 : total;

    // Higher-ranked neighbors (score desc, index asc) into registers.
    unsigned short js[NK];
    int nh = 0;
    {
        unsigned words[4] = {nv.x, nv.y, nv.z, nv.w};
        #pragma unroll
        for (int k = 0; k < NK; ++k) {
            if (k < cnt) {
                int j = (words[k >> 1] >> ((k & 1) * 16)) & 0xFFFF;
                float sj = ssc[j];
                if (sj > s || (sj == s && j < i)) js[nh++] = (unsigned short)j;
            }
        }
    }

    bool valid = s > 0.05f;
    if (!valid) {
        sstate[i] = 1;                // never kept, never suppresses
    } else if (!ovf && nh == 0) {
        sstate[i] = 2;                // top of its chain: kept
    } else {
        // Spin until all higher neighbors decided or one of them kept.
        // Monotone byte per box (0 -> 1|2): one volatile LDS per hop, no fences.
        // Min-rank undecided box always has all higher nbrs decided -> progress.
        const unsigned* adjT = g_adjT + (size_t)b * WORDS * AMAX;
        for (;;) {
            bool sup = false, alld = true;
            if (!ovf) {
                for (int k = 0; k < nh; ++k) {
                    unsigned char v = sstate[js[k]];
                    if (v == 2) { sup = true; break; }
                    if (v == 0) alld = false;
                }
            } else {
                #pragma unroll
                for (int w = 0; w < WORDS; ++w) {
                    unsigned mm = adjT[w * AMAX + i];
                    while (mm) {
                        int bit = __ffs(mm) - 1; mm &= mm - 1;
                        int j = w * 32 + bit;
                        float sj = ssc[j];
                        if (sj > s || (sj == s && j < i)) {
                            unsigned char v = sstate[j];
                            if (v == 2) { sup = true; }
                            else if (v == 0) alld = false;
                        }
                    }
                    if (sup) break;
                }
            }
            if (sup)  { sstate[i] = 1; break; }
            if (alld) { sstate[i] = 2; break; }
        }
    }
    __syncthreads();                  // all decided; sstate stable

    // Coalesced float4 output: 5120 floats/block = 1280 float4.
    const float* sboxf = (const float*)sbox;
    float4* obase4 = (float4*)(out + (size_t)bid * AMAX * 5);
    #pragma unroll
    for (int r = 0; r < 2; ++r) {
        int t = r * 1024 + i;
        if (t < (AMAX * 5) / 4) {
            float4 v;
            float* vf = (float*)&v;
            #pragma unroll
            for (int k = 0; k < 4; ++k) {
                int idx = t * 4 + k;
                int a = idx / 5;
                int f = idx - a * 5;
                float x = 0.0f;
                if (sstate[a] == 2) x = (f == 0) ? ssc[a] : sboxf[a * 4 + (f - 1)];
                vf[k] = x;
            }
            obase4[t] = v;
        }
    }
}

extern "C" void kernel_launch(void* const* d_in, const int* in_sizes, int n_in,
                              void* d_out, int out_size) {
    // metadata order: image, cls_pred, reg_pred, anchors
    const float* cls = (const float*)d_in[1];
    const float* reg = (const float*)d_in[2];
    const float* anchors = (const float*)d_in[3];

    int A = in_sizes[3] / 4;                 // 1024
    int B = in_sizes[2] / (4 * A);           // 2
    int C = in_sizes[1] / (B * A);           // 80
    long long hw = (long long)in_sizes[0] / (3LL * B);
    int H = (int)(sqrt((double)hw) + 0.5);   // 2048 (image used for shape only)
    float Hf = (float)H, Wf = (float)H;

    int nBlocks = B * C;                     // 160 blocks, all co-resident (2/SM)
    fused_kernel<<<nBlocks, 1024>>>(cls, reg, anchors, (float*)d_out,
                                    A, C, nBlocks, Wf, Hf);
}

// round 8
// speedup vs baseline: 1.5496x; 1.1358x over previous
#include <cuda_runtime.h>
#include <cmath>
#include <stdint.h>

#define AMAX 1024
#define WORDS 32
#define BMAX 2
#define CMAX 80
#define NK 8           // compact neighbor-list capacity (per box)
#define RPB 13         // ceil(1024/80) adjacency rows per block

// Scratch (static device arrays; no dynamic allocation allowed)
__device__ unsigned g_adjT[BMAX * WORDS * AMAX];          // 256 KB (fallback, degree>NK only)
__device__ unsigned short g_nbr[BMAX * AMAX * NK];        // 32 KB compact neighbor lists
__device__ int g_ncnt[BMAX * AMAX];                       // 8 KB degrees
__device__ int g_done[BMAX];                              // per-batch producer counters
__device__ int g_ack;                                     // replay-safe reset counter

__device__ __forceinline__ float4 regress_box(const float* __restrict__ reg,
                                              const float4* __restrict__ anchors4,
                                              int b, int t, int A, float Wf, float Hf) {
    float4 av = anchors4[t];                       // one LDG.128
    float w = av.z - av.x, h = av.w - av.y;
    float cx = av.x + 0.5f * w, cy = av.y + 0.5f * h;
    const float* rb = reg + (size_t)b * 4 * A;
    float dx = rb[0 * A + t] * 0.1f;
    float dy = rb[1 * A + t] * 0.1f;
    float dw = rb[2 * A + t] * 0.2f;
    float dh = rb[3 * A + t] * 0.2f;
    float pcx = cx + dx * w, pcy = cy + dy * h;
    float pw = expf(dw) * w, ph = expf(dh) * h;
    float4 r;
    r.x = fmaxf(pcx - 0.5f * pw, 0.0f);
    r.y = fmaxf(pcy - 0.5f * ph, 0.0f);
    r.z = fminf(pcx + 0.5f * pw, Wf);
    r.w = fminf(pcy + 0.5f * ph, Hf);
    return r;
}

// One fused kernel. Grid = B*C blocks x 1024 threads, one (b,c) each.
// Phase 1: warp w owns column-word w for the block's 13 rows (bj loop-invariant).
// Handoff: per-batch counter, volatile poll. Phase 2: async monotone-dataflow NMS.
__global__ void __launch_bounds__(1024, 2) fused_kernel(
    const float* __restrict__ cls, const float* __restrict__ reg,
    const float* __restrict__ anchors, float* __restrict__ out,
    int A, int C, int nBlocks, float Wf, float Hf) {
    __shared__ float4 sbox[AMAX];                   // 16 KB
    __shared__ float ssc[AMAX];                     // 4 KB
    __shared__ unsigned sadj[RPB * 32];             // 1.7 KB ballot tile [row][word]
    __shared__ volatile unsigned char sstate[AMAX]; // 0=undec, 1=dropped, 2=kept
    int bid = blockIdx.x;
    int i = threadIdx.x;
    int lane = i & 31, wid = i >> 5;
    int b = bid / C;
    int c = bid - b * C;
    int base = c * RPB;                             // first assigned row

    // Stage: regress own batch boxes (reused for phase 1, NMS, output) + scores.
    float s = cls[(size_t)bid * AMAX + i];
    sbox[i] = regress_box(reg, (const float4*)anchors, b, i, A, Wf, Hf);
    ssc[i] = s;
    sstate[i] = 0;
    __syncthreads();

    // ---- Phase 1a: all 32 warps; warp wid = column-word wid, rows serial ----
    {
        float4 bj = sbox[wid * 32 + lane];          // loop-invariant column box
        float ajj = (bj.z - bj.x) * (bj.w - bj.y);
        #pragma unroll
        for (int k = 0; k < RPB; ++k) {
            int row = base + k;
            if (row >= AMAX) break;
            float4 b0 = sbox[row];                  // broadcast LDS
            float a0 = (b0.z - b0.x) * (b0.w - b0.y);
            float i0 = fmaxf(fminf(b0.z, bj.z) - fmaxf(b0.x, bj.x), 0.0f) *
                       fmaxf(fminf(b0.w, bj.w) - fmaxf(b0.y, bj.y), 0.0f);
            // Conservative filter: IoU>0.5 => 3*inter > a0+aj (real arithmetic);
            // 0.999 margin absorbs fp rounding. Exact decision by IEEE div below
            // -> bit-identical results to the reference.
            bool c0 = 3.0f * i0 >= 0.999f * (a0 + ajj);
            bool adj0 = false;
            if (__any_sync(0xffffffffu, c0)) {      // rare path
                if (c0) adj0 = __fdiv_rn(i0, fmaxf((a0 + ajj) - i0, 1e-9f)) > 0.5f;
            }
            unsigned bal = __ballot_sync(0xffffffffu, adj0);
            if (lane == 0) sadj[k * 32 + wid] = bal;
        }
    }
    __syncthreads();

    // ---- Phase 1b: warps 0..RPB-1 emit row (base+wid): lists + rare fallback ----
    if (wid < RPB && base + wid < AMAX) {
        int row = base + wid;
        unsigned m = sadj[wid * 32 + lane];
        if (lane == (row >> 5)) m &= ~(1u << (row & 31));    // drop self bit

        int cnt = __popc(m);
        int scan = cnt;
        #pragma unroll
        for (int d = 1; d < 32; d <<= 1) {
            int t = __shfl_up_sync(0xffffffffu, scan, d);
            if (lane >= d) scan += t;
        }
        int excl = scan - cnt;
        int tot = __shfl_sync(0xffffffffu, scan, 31);
        unsigned short* np = g_nbr + ((size_t)b * AMAX + row) * NK;
        unsigned mm = m;
        int pos = excl;
        while (mm && pos < NK) {
            int t2 = __ffs(mm) - 1; mm &= mm - 1;
            np[pos++] = (unsigned short)(lane * 32 + t2);
        }
        if (lane == 0) g_ncnt[b * AMAX + row] = tot;
        if (tot > NK)                                      // fallback rows only
            g_adjT[((size_t)b * WORDS + lane) * AMAX + row] = m;
    }
    __syncthreads();                  // all this block's rows written (CTA HB)
    if (i == 0) {
        __threadfence();              // cumulative release (thread 0 only)
        atomicAdd(&g_done[b], 1);
        volatile int* dp = &g_done[b];
        while (*dp < C) __nanosleep(64);   // read-only poll
        __threadfence();              // acquire
        int a = atomicAdd(&g_ack, 1);
        if (a == nBlocks - 1) {       // last block past its wait: safe reset
            g_done[0] = 0; g_done[1] = 0;
            __threadfence();
            atomicExch(&g_ack, 0);
        }
    }
    __syncthreads();                  // adjacency for batch b visible to block

    // ---------------- Phase 2: async monotone-dataflow NMS ----------------
    int total = g_ncnt[b * AMAX + i];
    uint4 nv = *(const uint4*)&g_nbr[((size_t)b * AMAX + i) * NK];
    bool ovf = total > NK;            // rare high-degree fallback
    int cnt = ovf ? 0 : total;

    // Higher-ranked neighbors (score desc, index asc) into registers.
    unsigned short js[NK];
    int nh = 0;
    {
        unsigned words[4] = {nv.x, nv.y, nv.z, nv.w};
        #pragma unroll
        for (int k = 0; k < NK; ++k) {
            if (k < cnt) {
                int j = (words[k >> 1] >> ((k & 1) * 16)) & 0xFFFF;
                float sj = ssc[j];
                if (sj > s || (sj == s && j < i)) js[nh++] = (unsigned short)j;
            }
        }
    }

    bool valid = s > 0.05f;
    if (!valid) {
        sstate[i] = 1;                // never kept, never suppresses
    } else if (!ovf && nh == 0) {
        sstate[i] = 2;                // top of its chain: kept
    } else {
        // Spin until all higher neighbors decided or one of them kept.
        // Monotone byte per box (0 -> 1|2): one volatile LDS per hop, no fences.
        // Min-rank undecided box always has all higher nbrs decided -> progress.
        const unsigned* adjT = g_adjT + (size_t)b * WORDS * AMAX;
        for (;;) {
            bool sup = false, alld = true;
            if (!ovf) {
                for (int k = 0; k < nh; ++k) {
                    unsigned char v = sstate[js[k]];
                    if (v == 2) { sup = true; break; }
                    if (v == 0) alld = false;
                }
            } else {
                #pragma unroll
                for (int w = 0; w < WORDS; ++w) {
                    unsigned mm = adjT[w * AMAX + i];
                    while (mm) {
                        int bit = __ffs(mm) - 1; mm &= mm - 1;
                        int j = w * 32 + bit;
                        float sj = ssc[j];
                        if (sj > s || (sj == s && j < i)) {
                            unsigned char v = sstate[j];
                            if (v == 2) { sup = true; }
                            else if (v == 0) alld = false;
                        }
                    }
                    if (sup) break;
                }
            }
            if (sup)  { sstate[i] = 1; break; }
            if (alld) { sstate[i] = 2; break; }
        }
    }
    __syncthreads();                  // all decided; sstate stable

    // Coalesced float4 output: 5120 floats/block = 1280 float4.
    const float* sboxf = (const float*)sbox;
    float4* obase4 = (float4*)(out + (size_t)bid * AMAX * 5);
    #pragma unroll
    for (int r = 0; r < 2; ++r) {
        int t = r * 1024 + i;
        if (t < (AMAX * 5) / 4) {
            float4 v;
            float* vf = (float*)&v;
            #pragma unroll
            for (int k = 0; k < 4; ++k) {
                int idx = t * 4 + k;
                int a = idx / 5;
                int f = idx - a * 5;
                float x = 0.0f;
                if (sstate[a] == 2) x = (f == 0) ? ssc[a] : sboxf[a * 4 + (f - 1)];
                vf[k] = x;
            }
            obase4[t] = v;
        }
    }
}

extern "C" void kernel_launch(void* const* d_in, const int* in_sizes, int n_in,
                              void* d_out, int out_size) {
    // metadata order: image, cls_pred, reg_pred, anchors
    const float* cls = (const float*)d_in[1];
    const float* reg = (const float*)d_in[2];
    const float* anchors = (const float*)d_in[3];

    int A = in_sizes[3] / 4;                 // 1024
    int B = in_sizes[2] / (4 * A);           // 2
    int C = in_sizes[1] / (B * A);           // 80
    long long hw = (long long)in_sizes[0] / (3LL * B);
    int H = (int)(sqrt((double)hw) + 0.5);   // 2048 (image used for shape only)
    float Hf = (float)H, Wf = (float)H;

    int nBlocks = B * C;                     // 160 blocks, all co-resident (2/SM)
    fused_kernel<<<nBlocks, 1024>>>(cls, reg, anchors, (float*)d_out,
                                    A, C, nBlocks, Wf, Hf);
}

// round 9
// speedup vs baseline: 1.5529x; 1.0022x over previous
#include <cuda_runtime.h>
#include <cmath>
#include <stdint.h>

#define AMAX 1024
#define WORDS 32
#define BMAX 2
#define CMAX 80
#define NK 8           // compact neighbor-list capacity (per box)
#define RPB 13         // ceil(1024/80) adjacency rows per block

// Scratch (static device arrays; no dynamic allocation allowed)
__device__ unsigned g_adjT[BMAX * WORDS * AMAX];          // 256 KB (fallback, degree>NK only)
__device__ unsigned short g_nbr[BMAX * AMAX * NK];        // 32 KB compact neighbor lists
__device__ int g_ncnt[BMAX * AMAX];                       // 8 KB degrees
__device__ int g_done[BMAX];                              // monotone per-batch epoch counters

__device__ __forceinline__ float4 regress_box(const float* __restrict__ reg,
                                              const float4* __restrict__ anchors4,
                                              int b, int t, int A, float Wf, float Hf) {
    float4 av = anchors4[t];                       // one LDG.128
    float w = av.z - av.x, h = av.w - av.y;
    float cx = av.x + 0.5f * w, cy = av.y + 0.5f * h;
    const float* rb = reg + (size_t)b * 4 * A;
    float dx = rb[0 * A + t] * 0.1f;
    float dy = rb[1 * A + t] * 0.1f;
    float dw = rb[2 * A + t] * 0.2f;
    float dh = rb[3 * A + t] * 0.2f;
    float pcx = cx + dx * w, pcy = cy + dy * h;
    float pw = expf(dw) * w, ph = expf(dh) * h;
    float4 r;
    r.x = fmaxf(pcx - 0.5f * pw, 0.0f);
    r.y = fmaxf(pcy - 0.5f * ph, 0.0f);
    r.z = fminf(pcx + 0.5f * pw, Wf);
    r.w = fminf(pcy + 0.5f * ph, Hf);
    return r;
}

// One fused kernel. Grid = B*C blocks x 1024 threads, one (b,c) each.
// Phase 1: warp w owns column-word w; 2 rows per iteration, areas precomputed.
// Handoff: epoch-based monotone counter (no reset, replay-safe).
// Phase 2: async monotone-dataflow NMS; fused coalesced float4 output.
__global__ void __launch_bounds__(1024, 2) fused_kernel(
    const float* __restrict__ cls, const float* __restrict__ reg,
    const float* __restrict__ anchors, float* __restrict__ out,
    int A, int C, int nBlocks, float Wf, float Hf) {
    __shared__ float4 sbox[AMAX];                   // 16 KB
    __shared__ float ssc[AMAX];                     // 4 KB
    __shared__ float sarea[AMAX];                   // 4 KB box areas
    __shared__ unsigned sadj[RPB * 32];             // 1.7 KB ballot tile [row][word]
    __shared__ volatile unsigned char sstate[AMAX]; // 0=undec, 1=dropped, 2=kept
    int bid = blockIdx.x;
    int i = threadIdx.x;
    int lane = i & 31, wid = i >> 5;
    int b = bid / C;
    int c = bid - b * C;
    int base = c * RPB;                             // first assigned row

    // Stage: regress own batch boxes + areas + scores (reused everywhere).
    float s = cls[(size_t)bid * AMAX + i];
    float4 mybx = regress_box(reg, (const float4*)anchors, b, i, A, Wf, Hf);
    sbox[i] = mybx;
    sarea[i] = (mybx.z - mybx.x) * (mybx.w - mybx.y);  // same expr as before: bit-identical
    ssc[i] = s;
    sstate[i] = 0;
    __syncthreads();

    // ---- Phase 1a: warp wid = column-word wid; 2 rows per iteration ----
    {
        float4 bj = sbox[wid * 32 + lane];          // loop-invariant column box
        float ajj = sarea[wid * 32 + lane];
        #pragma unroll
        for (int k = 0; k + 1 < RPB; k += 2) {
            int r0 = base + k;
            if (r0 >= AMAX) break;
            bool h1 = (r0 + 1 < AMAX);
            float4 b0 = sbox[r0];
            float4 b1 = h1 ? sbox[r0 + 1] : b0;
            float a0 = sarea[r0];
            float a1 = h1 ? sarea[r0 + 1] : a0;
            float i0 = fmaxf(fminf(b0.z, bj.z) - fmaxf(b0.x, bj.x), 0.0f) *
                       fmaxf(fminf(b0.w, bj.w) - fmaxf(b0.y, bj.y), 0.0f);
            float i1 = fmaxf(fminf(b1.z, bj.z) - fmaxf(b1.x, bj.x), 0.0f) *
                       fmaxf(fminf(b1.w, bj.w) - fmaxf(b1.y, bj.y), 0.0f);
            // Conservative filter: IoU>0.5 => 3*inter > a+aj (real arithmetic);
            // 0.999 margin absorbs fp rounding. Exact decision via IEEE div
            // below -> bit-identical to reference.
            bool c0 = 3.0f * i0 >= 0.999f * (a0 + ajj);
            bool c1 = 3.0f * i1 >= 0.999f * (a1 + ajj);
            unsigned cb = __ballot_sync(0xffffffffu, c0 || c1);
            unsigned bal0 = 0, bal1 = 0;
            if (cb) {                                  // rare path (warp-uniform)
                bool adj0 = c0 && (__fdiv_rn(i0, fmaxf((a0 + ajj) - i0, 1e-9f)) > 0.5f);
                bool adj1 = c1 && (__fdiv_rn(i1, fmaxf((a1 + ajj) - i1, 1e-9f)) > 0.5f);
                bal0 = __ballot_sync(0xffffffffu, adj0);
                bal1 = __ballot_sync(0xffffffffu, adj1);
            }
            if (lane == 0) {
                sadj[k * 32 + wid] = bal0;
                if (h1) sadj[(k + 1) * 32 + wid] = bal1;
            }
        }
        {   // tail row (RPB odd)
            int r0 = base + RPB - 1;
            if (r0 < AMAX) {
                float4 b0 = sbox[r0];
                float a0 = sarea[r0];
                float i0 = fmaxf(fminf(b0.z, bj.z) - fmaxf(b0.x, bj.x), 0.0f) *
                           fmaxf(fminf(b0.w, bj.w) - fmaxf(b0.y, bj.y), 0.0f);
                bool c0 = 3.0f * i0 >= 0.999f * (a0 + ajj);
                unsigned cb = __ballot_sync(0xffffffffu, c0);
                unsigned bal0 = 0;
                if (cb) {
                    bool adj0 = c0 && (__fdiv_rn(i0, fmaxf((a0 + ajj) - i0, 1e-9f)) > 0.5f);
                    bal0 = __ballot_sync(0xffffffffu, adj0);
                }
                if (lane == 0) sadj[(RPB - 1) * 32 + wid] = bal0;
            }
        }
    }
    __syncthreads();

    // ---- Phase 1b: warps 0..RPB-1 emit row (base+wid): lists + rare fallback ----
    if (wid < RPB && base + wid < AMAX) {
        int row = base + wid;
        unsigned m = sadj[wid * 32 + lane];
        if (lane == (row >> 5)) m &= ~(1u << (row & 31));    // drop self bit

        int cnt = __popc(m);
        int scan = cnt;
        #pragma unroll
        for (int d = 1; d < 32; d <<= 1) {
            int t = __shfl_up_sync(0xffffffffu, scan, d);
            if (lane >= d) scan += t;
        }
        int excl = scan - cnt;
        int tot = __shfl_sync(0xffffffffu, scan, 31);
        unsigned short* np = g_nbr + ((size_t)b * AMAX + row) * NK;
        unsigned mm = m;
        int pos = excl;
        while (mm && pos < NK) {
            int t2 = __ffs(mm) - 1; mm &= mm - 1;
            np[pos++] = (unsigned short)(lane * 32 + t2);
        }
        if (lane == 0) g_ncnt[b * AMAX + row] = tot;
        if (tot > NK)                                      // fallback rows only
            g_adjT[((size_t)b * WORDS + lane) * AMAX + row] = m;
    }
    __syncthreads();                  // all this block's rows written (CTA HB)

    // ---- Handoff: epoch-based, monotone counter, no reset needed ----
    if (i == 0) {
        __threadfence();              // release (thread 0; bar gives CTA HB)
        int v = atomicAdd(&g_done[b], 1);        // v in [kC, kC+C-1] for epoch k
        int target = v - (v % C) + C;            // this launch's completion value
        volatile int* dp = &g_done[b];
        while (*dp < target) __nanosleep(64);    // read-only poll
        __threadfence();              // acquire
    }
    __syncthreads();                  // adjacency for batch b visible to block

    // ---------------- Phase 2: async monotone-dataflow NMS ----------------
    int total = g_ncnt[b * AMAX + i];
    uint4 nv = *(const uint4*)&g_nbr[((size_t)b * AMAX + i) * NK];
    bool ovf = total > NK;            // rare high-degree fallback
    int cnt = ovf ? 0 : total;

    // Higher-ranked neighbors (score desc, index asc) into registers.
    unsigned short js[NK];
    int nh = 0;
    {
        unsigned words[4] = {nv.x, nv.y, nv.z, nv.w};
        #pragma unroll
        for (int k = 0; k < NK; ++k) {
            if (k < cnt) {
                int j = (words[k >> 1] >> ((k & 1) * 16)) & 0xFFFF;
                float sj = ssc[j];
                if (sj > s || (sj == s && j < i)) js[nh++] = (unsigned short)j;
            }
        }
    }

    bool valid = s > 0.05f;
    if (!valid) {
        sstate[i] = 1;                // never kept, never suppresses
    } else if (!ovf && nh == 0) {
        sstate[i] = 2;                // top of its chain: kept
    } else {
        // Spin until all higher neighbors decided or one of them kept.
        // Monotone byte per box (0 -> 1|2): one volatile LDS per hop, no fences.
        // Min-rank undecided box always has all higher nbrs decided -> progress.
        const unsigned* adjT = g_adjT + (size_t)b * WORDS * AMAX;
        for (;;) {
            bool sup = false, alld = true;
            if (!ovf) {
                for (int k = 0; k < nh; ++k) {
                    unsigned char v = sstate[js[k]];
                    if (v == 2) { sup = true; break; }
                    if (v == 0) alld = false;
                }
            } else {
                #pragma unroll
                for (int w = 0; w < WORDS; ++w) {
                    unsigned mm = adjT[w * AMAX + i];
                    while (mm) {
                        int bit = __ffs(mm) - 1; mm &= mm - 1;
                        int j = w * 32 + bit;
                        float sj = ssc[j];
                        if (sj > s || (sj == s && j < i)) {
                            unsigned char v = sstate[j];
                            if (v == 2) { sup = true; }
                            else if (v == 0) alld = false;
                        }
                    }
                    if (sup) break;
                }
            }
            if (sup)  { sstate[i] = 1; break; }
            if (alld) { sstate[i] = 2; break; }
        }
    }
    __syncthreads();                  // all decided; sstate stable

    // Coalesced float4 output: 5120 floats/block = 1280 float4.
    const float* sboxf = (const float*)sbox;
    float4* obase4 = (float4*)(out + (size_t)bid * AMAX * 5);
    #pragma unroll
    for (int r = 0; r < 2; ++r) {
        int t = r * 1024 + i;
        if (t < (AMAX * 5) / 4) {
            float4 v;
            float* vf = (float*)&v;
            #pragma unroll
            for (int k = 0; k < 4; ++k) {
                int idx = t * 4 + k;
                int a = idx / 5;
                int f = idx - a * 5;
                float x = 0.0f;
                if (sstate[a] == 2) x = (f == 0) ? ssc[a] : sboxf[a * 4 + (f - 1)];
                vf[k] = x;
            }
            obase4[t] = v;
        }
    }
}

extern "C" void kernel_launch(void* const* d_in, const int* in_sizes, int n_in,
                              void* d_out, int out_size) {
    // metadata order: image, cls_pred, reg_pred, anchors
    const float* cls = (const float*)d_in[1];
    const float* reg = (const float*)d_in[2];
    const float* anchors = (const float*)d_in[3];

    int A = in_sizes[3] / 4;                 // 1024
    int B = in_sizes[2] / (4 * A);           // 2
    int C = in_sizes[1] / (B * A);           // 80
    long long hw = (long long)in_sizes[0] / (3LL * B);
    int H = (int)(sqrt((double)hw) + 0.5);   // 2048 (image used for shape only)
    float Hf = (float)H, Wf = (float)H;

    int nBlocks = B * C;                     // 160 blocks, all co-resident (2/SM)
    fused_kernel<<<nBlocks, 1024>>>(cls, reg, anchors, (float*)d_out,
                                    A, C, nBlocks, Wf, Hf);
}